// round 1
// baseline (speedup 1.0000x reference)
#include <cuda_runtime.h>

#define Nn 50000
#define Ee 800000
#define ET (Ee + Nn)      // 850000 edges incl. self-loops
#define Hh 2
#define Cc 64
#define HC 128            // Hh*Cc
#define NEG_SLOPE 0.2f

// ---------------- scratch (device globals; no allocation allowed) ----------------
__device__ float g_h[Nn * HC];      // transformed features for current layer [N,H,C]
__device__ float g_asrc[Nn * Hh];
__device__ float g_adst[Nn * Hh];
__device__ float g_m[Nn * Hh];      // segment max
__device__ float g_s[Nn * Hh];      // segment sum
__device__ float g_e[ET * Hh];      // per-edge logits / exp values
__device__ float g_acc[Nn * HC];    // scatter accumulator [N,H,C]
__device__ float g_x2[Nn * Cc];     // layer-1 output (layer-2 input)
__device__ float g_x3[Nn * Cc];     // layer-2 output

// ---------------- helpers ----------------
__device__ __forceinline__ void atomicMaxF(float* addr, float v) {
    // monotonic int/uint mapping trick; init value is -inf (0xFF800000)
    if (v >= 0.f) atomicMax((int*)addr, __float_as_int(v));
    else          atomicMin((unsigned int*)addr, __float_as_uint(v));
}

// ---------------- GEMM: Hout[N,128] = X[N,K] @ W[K,128] ----------------
template <int K>
__global__ void gemm_kernel(const float* __restrict__ X, const float* __restrict__ W) {
    __shared__ float xs[32][33];
    __shared__ float ws[32][128];
    const int c = threadIdx.x;          // output column 0..127
    const int row0 = blockIdx.x * 32;
    float acc[32];
#pragma unroll
    for (int r = 0; r < 32; r++) acc[r] = 0.f;

    for (int t = 0; t < K; t += 32) {
#pragma unroll
        for (int i = 0; i < 8; i++) {
            int e = c + i * 128;        // 0..1023
            int r = e >> 5, k = e & 31;
            int row = row0 + r;
            xs[r][k] = (row < Nn) ? X[row * K + t + k] : 0.f;
        }
#pragma unroll
        for (int kk = 0; kk < 32; kk++)
            ws[kk][c] = W[(t + kk) * 128 + c];
        __syncthreads();
#pragma unroll
        for (int kk = 0; kk < 32; kk++) {
            float wv = ws[kk][c];
#pragma unroll
            for (int r = 0; r < 32; r++) acc[r] += xs[r][kk] * wv;
        }
        __syncthreads();
    }
#pragma unroll
    for (int r = 0; r < 32; r++) {
        int row = row0 + r;
        if (row < Nn) g_h[row * 128 + c] = acc[r];
    }
}

// ---------------- attention coefficients: a_src/a_dst [N,H] ----------------
__global__ void att_kernel(const float* __restrict__ asv, const float* __restrict__ adv) {
    int warp = (blockIdx.x * blockDim.x + threadIdx.x) >> 5;
    int lane = threadIdx.x & 31;
    if (warp >= Nn * Hh) return;
    int n = warp >> 1, hh = warp & 1;
    const float* hp = g_h + n * HC + hh * Cc;
    float v1 = hp[lane], v2 = hp[32 + lane];
    float s1 = v1 * asv[hh * Cc + lane] + v2 * asv[hh * Cc + 32 + lane];
    float s2 = v1 * adv[hh * Cc + lane] + v2 * adv[hh * Cc + 32 + lane];
#pragma unroll
    for (int o = 16; o > 0; o >>= 1) {
        s1 += __shfl_down_sync(~0u, s1, o);
        s2 += __shfl_down_sync(~0u, s2, o);
    }
    if (lane == 0) { g_asrc[warp] = s1; g_adst[warp] = s2; }
}

// ---------------- init m=-inf, s=0, acc=0 ----------------
__global__ void init_kernel() {
    int i = blockIdx.x * blockDim.x + threadIdx.x;
    if (i < Nn * Hh) { g_m[i] = __int_as_float(0xFF800000); g_s[i] = 0.f; }
    if (i < Nn * HC) g_acc[i] = 0.f;
}

// ---------------- edge pass 1: logits + segment max ----------------
__global__ void edge_max_kernel(const int* __restrict__ ei) {
    int id = blockIdx.x * blockDim.x + threadIdx.x;
    if (id >= ET) return;
    int src, dst;
    if (id < Ee) { src = ei[id]; dst = ei[Ee + id]; }
    else         { src = dst = id - Ee; }
    float2 ev;
#pragma unroll
    for (int hh = 0; hh < 2; hh++) {
        float v = g_asrc[src * 2 + hh] + g_adst[dst * 2 + hh];
        v = v > 0.f ? v : NEG_SLOPE * v;
        ((float*)&ev)[hh] = v;
        atomicMaxF(&g_m[dst * 2 + hh], v);
    }
    *(float2*)(g_e + id * 2) = ev;
}

// ---------------- edge pass 2: exp + segment sum ----------------
__global__ void edge_expsum_kernel(const int* __restrict__ ei) {
    int id = blockIdx.x * blockDim.x + threadIdx.x;
    if (id >= ET) return;
    int dst = (id < Ee) ? ei[Ee + id] : id - Ee;
    float2 ev = *(const float2*)(g_e + id * 2);
#pragma unroll
    for (int hh = 0; hh < 2; hh++) {
        float v = __expf(((float*)&ev)[hh] - g_m[dst * 2 + hh]);
        ((float*)&ev)[hh] = v;
        atomicAdd(&g_s[dst * 2 + hh], v);
    }
    *(float2*)(g_e + id * 2) = ev;
}

// ---------------- edge pass 3: weighted scatter (warp per edge) ----------------
__global__ void scatter_kernel(const int* __restrict__ ei) {
    int gid = blockIdx.x * blockDim.x + threadIdx.x;
    int id = gid >> 5;
    int lane = gid & 31;
    if (id >= ET) return;
    int src, dst;
    if (id < Ee) { src = ei[id]; dst = ei[Ee + id]; }
    else         { src = dst = id - Ee; }
    int hh = lane >> 4;  // lane*4 in [0,124]; head = (lane*4)/64
    float alpha = g_e[id * 2 + hh] / (g_s[dst * 2 + hh] + 1e-16f);
    float4 hv = *(const float4*)(g_h + src * HC + lane * 4);
    float* ap = g_acc + dst * HC + lane * 4;
    atomicAdd(ap + 0, alpha * hv.x);
    atomicAdd(ap + 1, alpha * hv.y);
    atomicAdd(ap + 2, alpha * hv.z);
    atomicAdd(ap + 3, alpha * hv.w);
}

// ---------------- finalize: head mean + bias + relu ----------------
__global__ void finalize_kernel(const float* __restrict__ bias, float* __restrict__ out) {
    int i = blockIdx.x * blockDim.x + threadIdx.x;
    if (i >= Nn * Cc) return;
    int n = i >> 6, c = i & 63;
    float o = (g_acc[n * HC + c] + g_acc[n * HC + 64 + c]) * 0.5f + bias[c];
    out[i] = fmaxf(o, 0.f);
}

// ---------------- final linear head ----------------
__global__ void fc_kernel(const float* __restrict__ fcW, const float* __restrict__ fcb,
                          float* __restrict__ out) {
    int warp = (blockIdx.x * blockDim.x + threadIdx.x) >> 5;
    int lane = threadIdx.x & 31;
    if (warp >= Nn) return;
    float s = g_x3[warp * Cc + lane] * fcW[lane] + g_x3[warp * Cc + 32 + lane] * fcW[32 + lane];
#pragma unroll
    for (int o = 16; o > 0; o >>= 1) s += __shfl_down_sync(~0u, s, o);
    if (lane == 0) out[warp] = s + fcb[0];
}

// ---------------- host orchestration ----------------
static void run_layer(const float* xin, int K, const int* ei,
                      const float* W, const float* asv, const float* adv,
                      const float* b, float* xout) {
    if (K == 128) gemm_kernel<128><<<(Nn + 31) / 32, 128>>>(xin, W);
    else          gemm_kernel<64 ><<<(Nn + 31) / 32, 128>>>(xin, W);
    att_kernel<<<(Nn * Hh * 32 + 255) / 256, 256>>>(asv, adv);
    init_kernel<<<(Nn * HC + 255) / 256, 256>>>();
    edge_max_kernel<<<(ET + 255) / 256, 256>>>(ei);
    edge_expsum_kernel<<<(ET + 255) / 256, 256>>>(ei);
    scatter_kernel<<<(ET * 32 + 255) / 256, 256>>>(ei);
    finalize_kernel<<<(Nn * Cc + 255) / 256, 256>>>(b, xout);
}

extern "C" void kernel_launch(void* const* d_in, const int* in_sizes, int n_in,
                              void* d_out, int out_size) {
    const float* x        = (const float*)d_in[0];
    const int*   ei       = (const int*)  d_in[1];
    const float* W1       = (const float*)d_in[2];
    const float* att_src1 = (const float*)d_in[3];
    const float* att_dst1 = (const float*)d_in[4];
    const float* b1       = (const float*)d_in[5];
    const float* W2       = (const float*)d_in[6];
    const float* att_src2 = (const float*)d_in[7];
    const float* att_dst2 = (const float*)d_in[8];
    const float* b2       = (const float*)d_in[9];
    const float* fc_W     = (const float*)d_in[10];
    const float* fc_b     = (const float*)d_in[11];
    float* out = (float*)d_out;

    float *x2p = nullptr, *x3p = nullptr;
    cudaGetSymbolAddress((void**)&x2p, g_x2);
    cudaGetSymbolAddress((void**)&x3p, g_x3);

    run_layer(x,   128, ei, W1, att_src1, att_dst1, b1, x2p);
    run_layer(x2p, 64,  ei, W2, att_src2, att_dst2, b2, x3p);
    fc_kernel<<<(Nn * 32 + 255) / 256, 256>>>(fc_W, fc_b, out);
}

// round 2
// speedup vs baseline: 2.8280x; 2.8280x over previous
#include <cuda_runtime.h>
#include <math_constants.h>

#define Nn 50000
#define Ee 800000
#define ET (Ee + Nn)      // edges incl. self-loops
#define NEG_SLOPE 0.2f

// ---------------- scratch (device globals) ----------------
__device__ float  g_h[Nn * 128];     // transformed features [N,H*C]
__device__ float  g_x2[Nn * 64];     // layer-1 output
__device__ float  g_asrc[Nn * 2];
__device__ float  g_adst[Nn * 2];
__device__ float2 g_e[ET];           // per-edge logits -> exp values (2 heads)
__device__ int    g_deg[Nn];
__device__ int    g_cnt[Nn];
__device__ int    g_rowptr[Nn + 1];
__device__ int    g_src[ET];         // CSR-ordered (by dst) source ids
__device__ int    g_dstv[ET];        // CSR-ordered dst ids

// =================== CSR build (once per launch) ===================
__global__ void zero_kernel() {
    int i = blockIdx.x * blockDim.x + threadIdx.x;
    if (i < Nn) { g_deg[i] = 0; g_cnt[i] = 0; }
}

__global__ void hist_kernel(const int* __restrict__ ei) {
    int id = blockIdx.x * blockDim.x + threadIdx.x;
    if (id >= ET) return;
    int dst = (id < Ee) ? ei[Ee + id] : id - Ee;
    atomicAdd(&g_deg[dst], 1);
}

__global__ void scan_kernel() {       // exclusive prefix of deg -> rowptr
    __shared__ int part[1024];
    const int CH = (Nn + 1023) / 1024;
    int t = threadIdx.x;
    int base = t * CH;
    int sum = 0;
    for (int i = 0; i < CH; i++) {
        int idx = base + i;
        if (idx < Nn) sum += g_deg[idx];
    }
    part[t] = sum;
    __syncthreads();
    for (int off = 1; off < 1024; off <<= 1) {
        int v = (t >= off) ? part[t - off] : 0;
        __syncthreads();
        part[t] += v;
        __syncthreads();
    }
    int run = part[t] - sum;          // exclusive base for this chunk
    for (int i = 0; i < CH; i++) {
        int idx = base + i;
        if (idx < Nn) { g_rowptr[idx] = run; run += g_deg[idx]; }
    }
    if (t == 1023) g_rowptr[Nn] = part[1023];
}

__global__ void fill_kernel(const int* __restrict__ ei) {
    int id = blockIdx.x * blockDim.x + threadIdx.x;
    if (id >= ET) return;
    int src, dst;
    if (id < Ee) { src = ei[id]; dst = ei[Ee + id]; }
    else         { src = dst = id - Ee; }
    int pos = g_rowptr[dst] + atomicAdd(&g_cnt[dst], 1);
    g_src[pos]  = src;
    g_dstv[pos] = dst;
}

// =================== GEMM: g_h[N,128] = X[N,K] @ W[K,128] ===================
// 64x128 tile, 256 threads, thread tile 8x4, BK=32
template <int K>
__global__ void gemm_kernel(const float* __restrict__ X, const float* __restrict__ W) {
    __shared__ float xs[32][68];      // [kk][row], padded
    __shared__ float ws[32][128];
    const int t = threadIdx.x;
    const int row0 = blockIdx.x * 64;
    const int c0 = (t & 31) * 4;
    const int r0 = (t >> 5) * 8;
    float acc[8][4];
#pragma unroll
    for (int r = 0; r < 8; r++)
#pragma unroll
        for (int c = 0; c < 4; c++) acc[r][c] = 0.f;

    for (int kt = 0; kt < K; kt += 32) {
#pragma unroll
        for (int i = 0; i < 2; i++) {             // X tile: 64 rows x 32 k
            int q = t * 2 + i;                    // 0..511
            int r = q >> 3, kq = q & 7;
            int grow = row0 + r;
            float4 v = (grow < Nn) ? *(const float4*)&X[grow * K + kt + kq * 4]
                                   : make_float4(0.f, 0.f, 0.f, 0.f);
            xs[kq * 4 + 0][r] = v.x;
            xs[kq * 4 + 1][r] = v.y;
            xs[kq * 4 + 2][r] = v.z;
            xs[kq * 4 + 3][r] = v.w;
        }
#pragma unroll
        for (int i = 0; i < 4; i++) {             // W tile: 32 x 128
            int q = t + i * 256;
            int kk = q >> 5, cq = q & 31;
            *(float4*)&ws[kk][cq * 4] = *(const float4*)&W[(kt + kk) * 128 + cq * 4];
        }
        __syncthreads();
#pragma unroll
        for (int kk = 0; kk < 32; kk++) {
            float4 wv = *(float4*)&ws[kk][c0];
            float xr[8];
            *(float4*)&xr[0] = *(float4*)&xs[kk][r0];
            *(float4*)&xr[4] = *(float4*)&xs[kk][r0 + 4];
#pragma unroll
            for (int r = 0; r < 8; r++) {
                acc[r][0] += xr[r] * wv.x;
                acc[r][1] += xr[r] * wv.y;
                acc[r][2] += xr[r] * wv.z;
                acc[r][3] += xr[r] * wv.w;
            }
        }
        __syncthreads();
    }
#pragma unroll
    for (int r = 0; r < 8; r++) {
        int grow = row0 + r0 + r;
        if (grow < Nn)
            *(float4*)&g_h[grow * 128 + c0] =
                make_float4(acc[r][0], acc[r][1], acc[r][2], acc[r][3]);
    }
}

// =================== attention coefficients a_src/a_dst [N,2] ===================
__global__ void att_kernel(const float* __restrict__ asv, const float* __restrict__ adv) {
    int warp = (blockIdx.x * blockDim.x + threadIdx.x) >> 5;
    int lane = threadIdx.x & 31;
    if (warp >= Nn * 2) return;
    int n = warp >> 1, hh = warp & 1;
    const float* hp = g_h + n * 128 + hh * 64;
    float v1 = hp[lane], v2 = hp[32 + lane];
    float s1 = v1 * asv[hh * 64 + lane] + v2 * asv[hh * 64 + 32 + lane];
    float s2 = v1 * adv[hh * 64 + lane] + v2 * adv[hh * 64 + 32 + lane];
#pragma unroll
    for (int o = 16; o > 0; o >>= 1) {
        s1 += __shfl_down_sync(~0u, s1, o);
        s2 += __shfl_down_sync(~0u, s2, o);
    }
    if (lane == 0) { g_asrc[warp] = s1; g_adst[warp] = s2; }
}

// =================== per-edge logits into CSR order ===================
__global__ void logits_kernel() {
    int id = blockIdx.x * blockDim.x + threadIdx.x;
    if (id >= ET) return;
    int s = g_src[id], d = g_dstv[id];
    float2 as = *(const float2*)&g_asrc[s * 2];
    float2 ad = *(const float2*)&g_adst[d * 2];
    float e0 = as.x + ad.x;
    float e1 = as.y + ad.y;
    e0 = e0 > 0.f ? e0 : NEG_SLOPE * e0;
    e1 = e1 > 0.f ? e1 : NEG_SLOPE * e1;
    g_e[id] = make_float2(e0, e1);
}

// =================== warp-per-dst aggregate: softmax + gather + epilogue ===================
// FC=false: out = relu(mean_heads + bias)  -> [N,64]
// FC=true : out = (relu(mean_heads + bias)) @ fcW + fcb -> [N,1]
template <bool FC>
__global__ void aggregate_kernel(const float* __restrict__ bias,
                                 const float* __restrict__ fcW,
                                 const float* __restrict__ fcb,
                                 float* __restrict__ out) {
    int warp = (blockIdx.x * blockDim.x + threadIdx.x) >> 5;
    int lane = threadIdx.x & 31;
    if (warp >= Nn) return;
    int start = g_rowptr[warp], end = g_rowptr[warp + 1];

    // pass 1: max over incoming edges (both heads)
    float m0 = -CUDART_INF_F, m1 = -CUDART_INF_F;
    for (int i = start + lane; i < end; i += 32) {
        float2 ev = g_e[i];
        m0 = fmaxf(m0, ev.x);
        m1 = fmaxf(m1, ev.y);
    }
#pragma unroll
    for (int o = 16; o > 0; o >>= 1) {
        m0 = fmaxf(m0, __shfl_xor_sync(~0u, m0, o));
        m1 = fmaxf(m1, __shfl_xor_sync(~0u, m1, o));
    }

    // pass 2: exp + sum; write exp back
    float s0 = 0.f, s1 = 0.f;
    for (int i = start + lane; i < end; i += 32) {
        float2 ev = g_e[i];
        ev.x = __expf(ev.x - m0);
        ev.y = __expf(ev.y - m1);
        g_e[i] = ev;
        s0 += ev.x; s1 += ev.y;
    }
#pragma unroll
    for (int o = 16; o > 0; o >>= 1) {
        s0 += __shfl_xor_sync(~0u, s0, o);
        s1 += __shfl_xor_sync(~0u, s1, o);
    }
    __syncwarp();

    float inv = (lane < 16) ? 1.f / (s0 + 1e-16f) : 1.f / (s1 + 1e-16f);

    // pass 3: weighted gather; lane l covers channels 4l..4l+3
    float4 acc = make_float4(0.f, 0.f, 0.f, 0.f);
    for (int i = start; i < end; i++) {
        float2 ev = g_e[i];
        float a = ((lane < 16) ? ev.x : ev.y) * inv;
        int s = g_src[i];
        float4 hv = *(const float4*)&g_h[s * 128 + lane * 4];
        acc.x += a * hv.x;
        acc.y += a * hv.y;
        acc.z += a * hv.z;
        acc.w += a * hv.w;
    }

    // head mean: combine lane l with lane l^16
    float4 o4;
    o4.x = (acc.x + __shfl_xor_sync(~0u, acc.x, 16)) * 0.5f;
    o4.y = (acc.y + __shfl_xor_sync(~0u, acc.y, 16)) * 0.5f;
    o4.z = (acc.z + __shfl_xor_sync(~0u, acc.z, 16)) * 0.5f;
    o4.w = (acc.w + __shfl_xor_sync(~0u, acc.w, 16)) * 0.5f;

    if (!FC) {
        if (lane < 16) {
            float4 b4 = *(const float4*)&bias[lane * 4];
            o4.x = fmaxf(o4.x + b4.x, 0.f);
            o4.y = fmaxf(o4.y + b4.y, 0.f);
            o4.z = fmaxf(o4.z + b4.z, 0.f);
            o4.w = fmaxf(o4.w + b4.w, 0.f);
            *(float4*)&out[warp * 64 + lane * 4] = o4;
        }
    } else {
        float p = 0.f;
        if (lane < 16) {
            float4 b4 = *(const float4*)&bias[lane * 4];
            float4 w4 = *(const float4*)&fcW[lane * 4];
            p  = fmaxf(o4.x + b4.x, 0.f) * w4.x;
            p += fmaxf(o4.y + b4.y, 0.f) * w4.y;
            p += fmaxf(o4.z + b4.z, 0.f) * w4.z;
            p += fmaxf(o4.w + b4.w, 0.f) * w4.w;
        }
#pragma unroll
        for (int o = 8; o > 0; o >>= 1) p += __shfl_xor_sync(~0u, p, o);
        if (lane == 0) out[warp] = p + fcb[0];
    }
}

// =================== host orchestration ===================
extern "C" void kernel_launch(void* const* d_in, const int* in_sizes, int n_in,
                              void* d_out, int out_size) {
    const float* x        = (const float*)d_in[0];
    const int*   ei       = (const int*)  d_in[1];
    const float* W1       = (const float*)d_in[2];
    const float* att_src1 = (const float*)d_in[3];
    const float* att_dst1 = (const float*)d_in[4];
    const float* b1       = (const float*)d_in[5];
    const float* W2       = (const float*)d_in[6];
    const float* att_src2 = (const float*)d_in[7];
    const float* att_dst2 = (const float*)d_in[8];
    const float* b2       = (const float*)d_in[9];
    const float* fc_W     = (const float*)d_in[10];
    const float* fc_b     = (const float*)d_in[11];
    float* out = (float*)d_out;

    float* x2p = nullptr;
    cudaGetSymbolAddress((void**)&x2p, g_x2);

    // CSR build (graph identical for both layers)
    zero_kernel<<<(Nn + 255) / 256, 256>>>();
    hist_kernel<<<(ET + 255) / 256, 256>>>(ei);
    scan_kernel<<<1, 1024>>>();
    fill_kernel<<<(ET + 255) / 256, 256>>>(ei);

    // layer 1
    gemm_kernel<128><<<(Nn + 63) / 64, 256>>>(x, W1);
    att_kernel<<<(Nn * 2 * 32 + 255) / 256, 256>>>(att_src1, att_dst1);
    logits_kernel<<<(ET + 255) / 256, 256>>>();
    aggregate_kernel<false><<<(Nn * 32 + 255) / 256, 256>>>(b1, nullptr, nullptr, x2p);

    // layer 2 (+ fused final linear head)
    gemm_kernel<64><<<(Nn + 63) / 64, 256>>>(x2p, W2);
    att_kernel<<<(Nn * 2 * 32 + 255) / 256, 256>>>(att_src2, att_dst2);
    logits_kernel<<<(ET + 255) / 256, 256>>>();
    aggregate_kernel<true><<<(Nn * 32 + 255) / 256, 256>>>(b2, fc_W, fc_b, out);
}

// round 3
// speedup vs baseline: 2.9344x; 1.0376x over previous
#include <cuda_runtime.h>

#define Nn 50000
#define Ee 800000
#define ET (Ee + Nn)
#define NEG_SLOPE 0.2f

typedef unsigned int uint;

// ---------------- scratch ----------------
__device__ float  g_h[Nn * 128];
__device__ float  g_x2[Nn * 64];
__device__ float  g_asrc[Nn * 2];
__device__ float  g_adst[Nn * 2];
__device__ float2 g_e[ET];
__device__ int    g_deg[Nn];
__device__ int    g_rowptr[Nn + 1];
__device__ int    g_srcA[ET];
__device__ float4 g_Bh[16 * 256];   // fragment-packed W hi (max K=128: 16 ksteps x 8 tp x 32 lanes)
__device__ float4 g_Bl[16 * 256];

// ---------------- tf32 helpers ----------------
__device__ __forceinline__ uint tf32r(float x) {
    uint r; asm("cvt.rna.tf32.f32 %0, %1;" : "=r"(r) : "f"(x)); return r;
}
__device__ __forceinline__ void mma8(float* c, const uint* a, uint b0, uint b1) {
    asm volatile(
        "mma.sync.aligned.m16n8k8.row.col.f32.tf32.tf32.f32 "
        "{%0,%1,%2,%3},{%4,%5,%6,%7},{%8,%9},{%0,%1,%2,%3};"
        : "+f"(c[0]), "+f"(c[1]), "+f"(c[2]), "+f"(c[3])
        : "r"(a[0]), "r"(a[1]), "r"(a[2]), "r"(a[3]), "r"(b0), "r"(b1));
}

// =================== CSR build ===================
__global__ void zero_kernel() {
    int i = blockIdx.x * blockDim.x + threadIdx.x;
    if (i < Nn) g_deg[i] = 0;
}
__global__ void hist_kernel(const int* __restrict__ ei) {
    int id = blockIdx.x * blockDim.x + threadIdx.x;
    if (id >= ET) return;
    int dst = (id < Ee) ? ei[Ee + id] : id - Ee;
    atomicAdd(&g_deg[dst], 1);
}
__global__ void scan_kernel() {
    __shared__ int part[1024];
    const int CH = (Nn + 1023) / 1024;
    int t = threadIdx.x;
    int base = t * CH;
    int sum = 0;
    for (int i = 0; i < CH; i++) { int idx = base + i; if (idx < Nn) sum += g_deg[idx]; }
    part[t] = sum;
    __syncthreads();
    for (int off = 1; off < 1024; off <<= 1) {
        int v = (t >= off) ? part[t - off] : 0;
        __syncthreads();
        part[t] += v;
        __syncthreads();
    }
    int run = part[t] - sum;
    for (int i = 0; i < CH; i++) { int idx = base + i; if (idx < Nn) { g_rowptr[idx] = run; run += g_deg[idx]; } }
    if (t == 1023) g_rowptr[Nn] = part[1023];
}
__global__ void fill_kernel(const int* __restrict__ ei) {
    int id = blockIdx.x * blockDim.x + threadIdx.x;
    if (id >= ET) return;
    int src, dst;
    if (id < Ee) { src = ei[id]; dst = ei[Ee + id]; }
    else         { src = dst = id - Ee; }
    int old = atomicSub(&g_deg[dst], 1);
    g_srcA[g_rowptr[dst] + old - 1] = src;
}

// =================== B fragment prep (hi/lo tf32 split, mma layout) ===================
template <int K>
__global__ void bprep_kernel(const float* __restrict__ W) {
    int e = blockIdx.x * blockDim.x + threadIdx.x;
    if (e >= (K / 8) * 256) return;
    int ks   = e >> 8;
    int rem  = e & 255;
    int tp   = rem >> 5;
    int lane = rem & 31;
    int g = lane >> 2, t = lane & 3;
    int k0 = ks * 8 + t;
    int n0 = tp * 16 + g;
    float x = W[k0 * 128 + n0];
    float y = W[(k0 + 4) * 128 + n0];
    float z = W[k0 * 128 + n0 + 8];
    float w = W[(k0 + 4) * 128 + n0 + 8];
    uint hx = tf32r(x), hy = tf32r(y), hz = tf32r(z), hw = tf32r(w);
    float4 h4, l4;
    h4.x = __uint_as_float(hx); h4.y = __uint_as_float(hy);
    h4.z = __uint_as_float(hz); h4.w = __uint_as_float(hw);
    l4.x = __uint_as_float(tf32r(x - h4.x));
    l4.y = __uint_as_float(tf32r(y - h4.y));
    l4.z = __uint_as_float(tf32r(z - h4.z));
    l4.w = __uint_as_float(tf32r(w - h4.w));
    g_Bh[e] = h4;
    g_Bl[e] = l4;
}

// =================== GEMM (3xTF32) + fused attention dots ===================
// g_h[N,128] = X[N,K] @ W[K,128]; also writes g_asrc/g_adst [N,2]
template <int K>
__global__ void __launch_bounds__(128) gemm_att_kernel(const float* __restrict__ X,
                                                       const float* __restrict__ asv,
                                                       const float* __restrict__ adv) {
    int w = threadIdx.x >> 5, lane = threadIdx.x & 31;
    int g = lane >> 2, t = lane & 3;
    int rowb = blockIdx.x * 64 + w * 16;
    int r0 = rowb + g, r1 = r0 + 8;
    bool p0 = r0 < Nn, p1 = r1 < Nn;
    const float* x0 = X + (long)r0 * K + t;
    const float* x1 = X + (long)r1 * K + t;

    float acc[16][4] = {};
#pragma unroll
    for (int ks = 0; ks < K / 8; ks++) {
        float a0 = p0 ? x0[ks * 8]     : 0.f;
        float a2 = p0 ? x0[ks * 8 + 4] : 0.f;
        float a1 = p1 ? x1[ks * 8]     : 0.f;
        float a3 = p1 ? x1[ks * 8 + 4] : 0.f;
        uint ah[4], al[4];
        ah[0] = tf32r(a0); al[0] = tf32r(a0 - __uint_as_float(ah[0]));
        ah[1] = tf32r(a1); al[1] = tf32r(a1 - __uint_as_float(ah[1]));
        ah[2] = tf32r(a2); al[2] = tf32r(a2 - __uint_as_float(ah[2]));
        ah[3] = tf32r(a3); al[3] = tf32r(a3 - __uint_as_float(ah[3]));

        const float4* bh = g_Bh + ks * 256 + lane;
        const float4* bl = g_Bl + ks * 256 + lane;
#pragma unroll
        for (int tp = 0; tp < 8; tp++) {
            float4 h4 = bh[tp * 32];
            float4 l4 = bl[tp * 32];
            uint bh0 = __float_as_uint(h4.x), bh1 = __float_as_uint(h4.y);
            uint bl0 = __float_as_uint(l4.x), bl1 = __float_as_uint(l4.y);
            mma8(acc[2 * tp], ah, bh0, bh1);
            mma8(acc[2 * tp], ah, bl0, bl1);
            mma8(acc[2 * tp], al, bh0, bh1);
            uint ch0 = __float_as_uint(h4.z), ch1 = __float_as_uint(h4.w);
            uint cl0 = __float_as_uint(l4.z), cl1 = __float_as_uint(l4.w);
            mma8(acc[2 * tp + 1], ah, ch0, ch1);
            mma8(acc[2 * tp + 1], ah, cl0, cl1);
            mma8(acc[2 * tp + 1], al, ch0, ch1);
        }
    }

    // store h
#pragma unroll
    for (int n = 0; n < 16; n++) {
        if (p0) *(float2*)&g_h[(long)r0 * 128 + n * 8 + 2 * t] = make_float2(acc[n][0], acc[n][1]);
        if (p1) *(float2*)&g_h[(long)r1 * 128 + n * 8 + 2 * t] = make_float2(acc[n][2], acc[n][3]);
    }

    // fused attention dot products
    float sa[2][2] = {};   // [rowhalf][head]
    float sd[2][2] = {};
#pragma unroll
    for (int n = 0; n < 16; n++) {
        int c = n * 8 + 2 * t;
        float v0 = asv[c], v1 = asv[c + 1];
        float u0 = adv[c], u1 = adv[c + 1];
        int hh = n >> 3;
        sa[0][hh] += acc[n][0] * v0 + acc[n][1] * v1;
        sa[1][hh] += acc[n][2] * v0 + acc[n][3] * v1;
        sd[0][hh] += acc[n][0] * u0 + acc[n][1] * u1;
        sd[1][hh] += acc[n][2] * u0 + acc[n][3] * u1;
    }
#pragma unroll
    for (int rh = 0; rh < 2; rh++)
#pragma unroll
        for (int hh = 0; hh < 2; hh++) {
            sa[rh][hh] += __shfl_xor_sync(~0u, sa[rh][hh], 1);
            sa[rh][hh] += __shfl_xor_sync(~0u, sa[rh][hh], 2);
            sd[rh][hh] += __shfl_xor_sync(~0u, sd[rh][hh], 1);
            sd[rh][hh] += __shfl_xor_sync(~0u, sd[rh][hh], 2);
        }
    if (t == 0) {
        if (p0) {
            g_asrc[r0 * 2] = sa[0][0]; g_asrc[r0 * 2 + 1] = sa[0][1];
            g_adst[r0 * 2] = sd[0][0]; g_adst[r0 * 2 + 1] = sd[0][1];
        }
        if (p1) {
            g_asrc[r1 * 2] = sa[1][0]; g_asrc[r1 * 2 + 1] = sa[1][1];
            g_adst[r1 * 2] = sd[1][0]; g_adst[r1 * 2 + 1] = sd[1][1];
        }
    }
}

// =================== aggregate: logits + softmax + gather + epilogue ===================
template <bool FC>
__global__ void aggregate_kernel(const float* __restrict__ bias,
                                 const float* __restrict__ fcW,
                                 const float* __restrict__ fcb,
                                 float* __restrict__ out) {
    int warp = (blockIdx.x * blockDim.x + threadIdx.x) >> 5;
    int lane = threadIdx.x & 31;
    if (warp >= Nn) return;
    int start = g_rowptr[warp], end = g_rowptr[warp + 1];
    float2 ad = *(const float2*)&g_adst[warp * 2];

    // pass 1: logits + exp + sum (lane-strided); keep first chunk in registers
    float s0 = 0.f, s1 = 0.f;
    int   fsrc = 0;
    float fp0 = 0.f, fp1 = 0.f;
    int i0 = start + lane;
    if (i0 < end) {
        int s = g_srcA[i0];
        float2 as = *(const float2*)&g_asrc[s * 2];
        float e0 = as.x + ad.x; e0 = e0 > 0.f ? e0 : NEG_SLOPE * e0;
        float e1 = as.y + ad.y; e1 = e1 > 0.f ? e1 : NEG_SLOPE * e1;
        fp0 = __expf(fminf(e0, 60.f));
        fp1 = __expf(fminf(e1, 60.f));
        fsrc = s;
        s0 += fp0; s1 += fp1;
        for (int i = i0 + 32; i < end; i += 32) {
            int s2 = g_srcA[i];
            float2 a2 = *(const float2*)&g_asrc[s2 * 2];
            float q0 = a2.x + ad.x; q0 = q0 > 0.f ? q0 : NEG_SLOPE * q0;
            float q1 = a2.y + ad.y; q1 = q1 > 0.f ? q1 : NEG_SLOPE * q1;
            q0 = __expf(fminf(q0, 60.f));
            q1 = __expf(fminf(q1, 60.f));
            g_e[i] = make_float2(q0, q1);
            s0 += q0; s1 += q1;
        }
    }
#pragma unroll
    for (int o = 16; o > 0; o >>= 1) {
        s0 += __shfl_xor_sync(~0u, s0, o);
        s1 += __shfl_xor_sync(~0u, s1, o);
    }
    float inv = (lane < 16) ? 1.f / (s0 + 1e-16f) : 1.f / (s1 + 1e-16f);

    // pass 2: weighted gather; lane covers channels 4*lane..4*lane+3
    float4 acc = make_float4(0.f, 0.f, 0.f, 0.f);
    int cn = min(32, end - start);
    for (int j = 0; j < cn; j++) {
        int   s  = __shfl_sync(~0u, fsrc, j);
        float q0 = __shfl_sync(~0u, fp0, j);
        float q1 = __shfl_sync(~0u, fp1, j);
        float a = ((lane < 16) ? q0 : q1) * inv;
        float4 hv = *(const float4*)&g_h[(long)s * 128 + lane * 4];
        acc.x += a * hv.x; acc.y += a * hv.y; acc.z += a * hv.z; acc.w += a * hv.w;
    }
    for (int base = start + 32; base < end; base += 32) {
        int idx = base + lane;
        int   ls = (idx < end) ? g_srcA[idx] : 0;
        float lp0 = 0.f, lp1 = 0.f;
        if (idx < end) { float2 ev = g_e[idx]; lp0 = ev.x; lp1 = ev.y; }
        int n = min(32, end - base);
        for (int j = 0; j < n; j++) {
            int   s  = __shfl_sync(~0u, ls, j);
            float q0 = __shfl_sync(~0u, lp0, j);
            float q1 = __shfl_sync(~0u, lp1, j);
            float a = ((lane < 16) ? q0 : q1) * inv;
            float4 hv = *(const float4*)&g_h[(long)s * 128 + lane * 4];
            acc.x += a * hv.x; acc.y += a * hv.y; acc.z += a * hv.z; acc.w += a * hv.w;
        }
    }

    // head mean
    float4 o4;
    o4.x = (acc.x + __shfl_xor_sync(~0u, acc.x, 16)) * 0.5f;
    o4.y = (acc.y + __shfl_xor_sync(~0u, acc.y, 16)) * 0.5f;
    o4.z = (acc.z + __shfl_xor_sync(~0u, acc.z, 16)) * 0.5f;
    o4.w = (acc.w + __shfl_xor_sync(~0u, acc.w, 16)) * 0.5f;

    if (!FC) {
        if (lane < 16) {
            float4 b4 = *(const float4*)&bias[lane * 4];
            o4.x = fmaxf(o4.x + b4.x, 0.f);
            o4.y = fmaxf(o4.y + b4.y, 0.f);
            o4.z = fmaxf(o4.z + b4.z, 0.f);
            o4.w = fmaxf(o4.w + b4.w, 0.f);
            *(float4*)&out[(long)warp * 64 + lane * 4] = o4;
        }
    } else {
        float p = 0.f;
        if (lane < 16) {
            float4 b4 = *(const float4*)&bias[lane * 4];
            float4 w4 = *(const float4*)&fcW[lane * 4];
            p  = fmaxf(o4.x + b4.x, 0.f) * w4.x;
            p += fmaxf(o4.y + b4.y, 0.f) * w4.y;
            p += fmaxf(o4.z + b4.z, 0.f) * w4.z;
            p += fmaxf(o4.w + b4.w, 0.f) * w4.w;
        }
#pragma unroll
        for (int o = 8; o > 0; o >>= 1) p += __shfl_xor_sync(~0u, p, o);
        if (lane == 0) out[warp] = p + fcb[0];
    }
}

// =================== host orchestration ===================
extern "C" void kernel_launch(void* const* d_in, const int* in_sizes, int n_in,
                              void* d_out, int out_size) {
    const float* x        = (const float*)d_in[0];
    const int*   ei       = (const int*)  d_in[1];
    const float* W1       = (const float*)d_in[2];
    const float* att_src1 = (const float*)d_in[3];
    const float* att_dst1 = (const float*)d_in[4];
    const float* b1       = (const float*)d_in[5];
    const float* W2       = (const float*)d_in[6];
    const float* att_src2 = (const float*)d_in[7];
    const float* att_dst2 = (const float*)d_in[8];
    const float* b2       = (const float*)d_in[9];
    const float* fc_W     = (const float*)d_in[10];
    const float* fc_b     = (const float*)d_in[11];
    float* out = (float*)d_out;

    float* x2p = nullptr;
    cudaGetSymbolAddress((void**)&x2p, g_x2);

    // CSR build
    zero_kernel<<<(Nn + 255) / 256, 256>>>();
    hist_kernel<<<(ET + 255) / 256, 256>>>(ei);
    scan_kernel<<<1, 1024>>>();
    fill_kernel<<<(ET + 255) / 256, 256>>>(ei);

    // layer 1
    bprep_kernel<128><<<(16 * 256 + 255) / 256, 256>>>(W1);
    gemm_att_kernel<128><<<(Nn + 63) / 64, 128>>>(x, att_src1, att_dst1);
    aggregate_kernel<false><<<(Nn * 32 + 255) / 256, 256>>>(b1, nullptr, nullptr, x2p);

    // layer 2 (+ fused FC head)
    bprep_kernel<64><<<(8 * 256 + 255) / 256, 256>>>(W2);
    gemm_att_kernel<64><<<(Nn + 63) / 64, 128>>>(x2p, att_src2, att_dst2);
    aggregate_kernel<true><<<(Nn * 32 + 255) / 256, 256>>>(b2, fc_W, fc_b, out);
}

// round 5
// speedup vs baseline: 4.9623x; 1.6911x over previous
#include <cuda_runtime.h>
#include <cuda_fp16.h>

#define Nn 50000
#define Ee 800000
#define ET (Ee + Nn)
#define NEG_SLOPE 0.2f
#define NB 196              // scan blocks: 196*256 >= 50000

typedef unsigned int uint;

// ---------------- scratch ----------------
__device__ uint   g_hh[Nn * 64];     // h as half2 units: 128 halves per node
__device__ uint   g_x2h[Nn * 32];    // layer-1 output as half2 units (64 halves per node)
__device__ float  g_asrc[Nn * 2];
__device__ float  g_adst[Nn * 2];
__device__ float2 g_e[ET];
__device__ int    g_deg[Nn];
__device__ int    g_part[NB];
__device__ int    g_rowptr[Nn + 1];
__device__ int    g_srcA[ET];
__device__ uint2  g_Bp[8 * 16 * 32]; // fragment-packed W halves (max K=128)

// ---------------- helpers ----------------
__device__ __forceinline__ uint packh2(float a, float b) {
    __half2 h = __floats2half2_rn(a, b);
    return *(uint*)&h;
}
__device__ __forceinline__ void mma16(float* c, const uint* a, uint b0, uint b1) {
    asm volatile(
        "mma.sync.aligned.m16n8k16.row.col.f32.f16.f16.f32 "
        "{%0,%1,%2,%3},{%4,%5,%6,%7},{%8,%9},{%0,%1,%2,%3};"
        : "+f"(c[0]), "+f"(c[1]), "+f"(c[2]), "+f"(c[3])
        : "r"(a[0]), "r"(a[1]), "r"(a[2]), "r"(a[3]), "r"(b0), "r"(b1));
}

// =================== CSR build ===================
__global__ void zero_kernel() {
    int i = blockIdx.x * blockDim.x + threadIdx.x;
    if (i < Nn) g_deg[i] = 0;
}
__global__ void hist_kernel(const int* __restrict__ ei) {
    int id = blockIdx.x * blockDim.x + threadIdx.x;
    if (id >= ET) return;
    int dst = (id < Ee) ? ei[Ee + id] : id - Ee;
    atomicAdd(&g_deg[dst], 1);
}
__global__ void scan1_kernel() {                 // per-block sums
    __shared__ int sm[256];
    int t = threadIdx.x;
    int i = blockIdx.x * 256 + t;
    sm[t] = (i < Nn) ? g_deg[i] : 0;
    __syncthreads();
    for (int o = 128; o > 0; o >>= 1) {
        if (t < o) sm[t] += sm[t + o];
        __syncthreads();
    }
    if (t == 0) g_part[blockIdx.x] = sm[0];
}
__global__ void scan2_kernel() {                 // per-block scan + global offset
    __shared__ int sp[256];
    __shared__ int sd[256];
    int b = blockIdx.x, t = threadIdx.x;
    sp[t] = (t < NB && t < b) ? g_part[t] : 0;
    __syncthreads();
    for (int o = 128; o > 0; o >>= 1) {
        if (t < o) sp[t] += sp[t + o];
        __syncthreads();
    }
    int base = sp[0];
    int i = b * 256 + t;
    int v = (i < Nn) ? g_deg[i] : 0;
    sd[t] = v;
    __syncthreads();
    for (int o = 1; o < 256; o <<= 1) {
        int y = (t >= o) ? sd[t - o] : 0;
        __syncthreads();
        sd[t] += y;
        __syncthreads();
    }
    if (i < Nn) g_rowptr[i] = base + sd[t] - v;  // exclusive
    if (b == NB - 1 && t == 255) g_rowptr[Nn] = base + sd[255];
}
__global__ void fill_kernel(const int* __restrict__ ei) {
    int id = blockIdx.x * blockDim.x + threadIdx.x;
    if (id >= ET) return;
    int src, dst;
    if (id < Ee) { src = ei[id]; dst = ei[Ee + id]; }
    else         { src = dst = id - Ee; }
    int old = atomicSub(&g_deg[dst], 1);
    g_srcA[g_rowptr[dst] + old - 1] = src;
}

// =================== B fragment prep (fp16, m16n8k16 layout) ===================
template <int K>
__global__ void bprep_kernel(const float* __restrict__ W) {
    int e = blockIdx.x * blockDim.x + threadIdx.x;
    if (e >= (K / 16) * 512) return;
    int ks   = e >> 9;
    int rem  = e & 511;
    int tp   = rem >> 5;
    int lane = rem & 31;
    int g = lane >> 2, t = lane & 3;
    int k0 = ks * 16 + 2 * t;
    int n  = tp * 8 + g;
    uint2 p;
    p.x = packh2(W[k0 * 128 + n],       W[(k0 + 1) * 128 + n]);
    p.y = packh2(W[(k0 + 8) * 128 + n], W[(k0 + 9) * 128 + n]);
    g_Bp[e] = p;
}

// =================== GEMM (fp16 HMMA, fp32 acc) + fused attention dots ===================
template <int K, bool HALF_IN>
__global__ void __launch_bounds__(128) gemm_att_kernel(const void* __restrict__ Xv,
                                                       const float* __restrict__ asv,
                                                       const float* __restrict__ adv) {
    int w = threadIdx.x >> 5, lane = threadIdx.x & 31;
    int g = lane >> 2, t = lane & 3;
    int rowb = blockIdx.x * 64 + w * 16;
    int r0 = rowb + g, r1 = r0 + 8;
    bool p0 = r0 < Nn, p1 = r1 < Nn;
    const float* Xf = (const float*)Xv;
    const uint*  Xh = (const uint*)Xv;     // half2 units

    float acc[16][4] = {};
#pragma unroll
    for (int ks = 0; ks < K / 16; ks++) {
        int kA = ks * 16 + 2 * t;
        uint a[4];
        if (HALF_IN) {
            a[0] = p0 ? Xh[(r0 * K + kA) >> 1]     : 0u;
            a[1] = p1 ? Xh[(r1 * K + kA) >> 1]     : 0u;
            a[2] = p0 ? Xh[(r0 * K + kA + 8) >> 1] : 0u;
            a[3] = p1 ? Xh[(r1 * K + kA + 8) >> 1] : 0u;
        } else {
            float2 f0 = p0 ? *(const float2*)&Xf[r0 * K + kA]     : make_float2(0.f, 0.f);
            float2 f1 = p1 ? *(const float2*)&Xf[r1 * K + kA]     : make_float2(0.f, 0.f);
            float2 f2 = p0 ? *(const float2*)&Xf[r0 * K + kA + 8] : make_float2(0.f, 0.f);
            float2 f3 = p1 ? *(const float2*)&Xf[r1 * K + kA + 8] : make_float2(0.f, 0.f);
            a[0] = packh2(f0.x, f0.y);
            a[1] = packh2(f1.x, f1.y);
            a[2] = packh2(f2.x, f2.y);
            a[3] = packh2(f3.x, f3.y);
        }
        const uint2* bp = g_Bp + ks * 512 + lane;
#pragma unroll
        for (int tp = 0; tp < 16; tp++) {
            uint2 b = bp[tp * 32];
            mma16(acc[tp], a, b.x, b.y);
        }
    }

    // store h as half
#pragma unroll
    for (int n = 0; n < 16; n++) {
        int c = n * 8 + 2 * t;
        if (p0) g_hh[(r0 * 128 + c) >> 1] = packh2(acc[n][0], acc[n][1]);
        if (p1) g_hh[(r1 * 128 + c) >> 1] = packh2(acc[n][2], acc[n][3]);
    }

    // fused attention dots (fp32 accumulators)
    float sa[2][2] = {};
    float sd_[2][2] = {};
#pragma unroll
    for (int n = 0; n < 16; n++) {
        int c = n * 8 + 2 * t;
        float v0 = asv[c], v1 = asv[c + 1];
        float u0 = adv[c], u1 = adv[c + 1];
        int hh = n >> 3;
        sa[0][hh] += acc[n][0] * v0 + acc[n][1] * v1;
        sa[1][hh] += acc[n][2] * v0 + acc[n][3] * v1;
        sd_[0][hh] += acc[n][0] * u0 + acc[n][1] * u1;
        sd_[1][hh] += acc[n][2] * u0 + acc[n][3] * u1;
    }
#pragma unroll
    for (int rh = 0; rh < 2; rh++)
#pragma unroll
        for (int hh = 0; hh < 2; hh++) {
            sa[rh][hh] += __shfl_xor_sync(~0u, sa[rh][hh], 1);
            sa[rh][hh] += __shfl_xor_sync(~0u, sa[rh][hh], 2);
            sd_[rh][hh] += __shfl_xor_sync(~0u, sd_[rh][hh], 1);
            sd_[rh][hh] += __shfl_xor_sync(~0u, sd_[rh][hh], 2);
        }
    if (t == 0) {
        if (p0) {
            g_asrc[r0 * 2] = sa[0][0]; g_asrc[r0 * 2 + 1] = sa[0][1];
            g_adst[r0 * 2] = sd_[0][0]; g_adst[r0 * 2 + 1] = sd_[0][1];
        }
        if (p1) {
            g_asrc[r1 * 2] = sa[1][0]; g_asrc[r1 * 2 + 1] = sa[1][1];
            g_adst[r1 * 2] = sd_[1][0]; g_adst[r1 * 2 + 1] = sd_[1][1];
        }
    }
}

// =================== aggregate: logits + softmax + fp16 gather + epilogue ===================
template <bool FC>
__global__ void aggregate_kernel(const float* __restrict__ bias,
                                 const float* __restrict__ fcW,
                                 const float* __restrict__ fcb,
                                 float* __restrict__ out) {
    int warp = (blockIdx.x * blockDim.x + threadIdx.x) >> 5;
    int lane = threadIdx.x & 31;
    if (warp >= Nn) return;
    int start = g_rowptr[warp], end = g_rowptr[warp + 1];
    float2 ad = *(const float2*)&g_adst[warp * 2];

    // pass 1: logits + exp + sum; first chunk kept in registers
    float s0 = 0.f, s1 = 0.f;
    int   fsrc = 0;
    float fp0 = 0.f, fp1 = 0.f;
    int i0 = start + lane;
    if (i0 < end) {
        int s = g_srcA[i0];
        float2 as = *(const float2*)&g_asrc[s * 2];
        float e0 = as.x + ad.x; e0 = e0 > 0.f ? e0 : NEG_SLOPE * e0;
        float e1 = as.y + ad.y; e1 = e1 > 0.f ? e1 : NEG_SLOPE * e1;
        fp0 = __expf(fminf(e0, 60.f));
        fp1 = __expf(fminf(e1, 60.f));
        fsrc = s;
        s0 += fp0; s1 += fp1;
        for (int i = i0 + 32; i < end; i += 32) {
            int s2 = g_srcA[i];
            float2 a2 = *(const float2*)&g_asrc[s2 * 2];
            float q0 = a2.x + ad.x; q0 = q0 > 0.f ? q0 : NEG_SLOPE * q0;
            float q1 = a2.y + ad.y; q1 = q1 > 0.f ? q1 : NEG_SLOPE * q1;
            q0 = __expf(fminf(q0, 60.f));
            q1 = __expf(fminf(q1, 60.f));
            g_e[i] = make_float2(q0, q1);
            s0 += q0; s1 += q1;
        }
    }
#pragma unroll
    for (int o = 16; o > 0; o >>= 1) {
        s0 += __shfl_xor_sync(~0u, s0, o);
        s1 += __shfl_xor_sync(~0u, s1, o);
    }
    float inv = (lane < 16) ? 1.f / (s0 + 1e-16f) : 1.f / (s1 + 1e-16f);

    // pass 2: weighted fp16 gather; lane covers channels 4*lane..4*lane+3
    float4 acc = make_float4(0.f, 0.f, 0.f, 0.f);
    int cn = min(32, end - start);
    for (int j = 0; j < cn; j++) {
        int   s  = __shfl_sync(~0u, fsrc, j);
        float q0 = __shfl_sync(~0u, fp0, j);
        float q1 = __shfl_sync(~0u, fp1, j);
        float a = ((lane < 16) ? q0 : q1) * inv;
        uint2 hu = *(const uint2*)&g_hh[s * 64 + lane * 2];
        float2 f0 = __half22float2(*(__half2*)&hu.x);
        float2 f1 = __half22float2(*(__half2*)&hu.y);
        acc.x += a * f0.x; acc.y += a * f0.y; acc.z += a * f1.x; acc.w += a * f1.y;
    }
    for (int base = start + 32; base < end; base += 32) {
        int idx = base + lane;
        int   ls = (idx < end) ? g_srcA[idx] : 0;
        float lp0 = 0.f, lp1 = 0.f;
        if (idx < end) { float2 ev = g_e[idx]; lp0 = ev.x; lp1 = ev.y; }
        int n = min(32, end - base);
        for (int j = 0; j < n; j++) {
            int   s  = __shfl_sync(~0u, ls, j);
            float q0 = __shfl_sync(~0u, lp0, j);
            float q1 = __shfl_sync(~0u, lp1, j);
            float a = ((lane < 16) ? q0 : q1) * inv;
            uint2 hu = *(const uint2*)&g_hh[s * 64 + lane * 2];
            float2 f0 = __half22float2(*(__half2*)&hu.x);
            float2 f1 = __half22float2(*(__half2*)&hu.y);
            acc.x += a * f0.x; acc.y += a * f0.y; acc.z += a * f1.x; acc.w += a * f1.y;
        }
    }

    // head mean
    float4 o4;
    o4.x = (acc.x + __shfl_xor_sync(~0u, acc.x, 16)) * 0.5f;
    o4.y = (acc.y + __shfl_xor_sync(~0u, acc.y, 16)) * 0.5f;
    o4.z = (acc.z + __shfl_xor_sync(~0u, acc.z, 16)) * 0.5f;
    o4.w = (acc.w + __shfl_xor_sync(~0u, acc.w, 16)) * 0.5f;

    if (!FC) {
        if (lane < 16) {
            float4 b4 = *(const float4*)&bias[lane * 4];
            o4.x = fmaxf(o4.x + b4.x, 0.f);
            o4.y = fmaxf(o4.y + b4.y, 0.f);
            o4.z = fmaxf(o4.z + b4.z, 0.f);
            o4.w = fmaxf(o4.w + b4.w, 0.f);
            uint2 p;
            p.x = packh2(o4.x, o4.y);
            p.y = packh2(o4.z, o4.w);
            *(uint2*)&((uint*)out)[warp * 32 + lane * 2] = p;
        }
    } else {
        float p = 0.f;
        if (lane < 16) {
            float4 b4 = *(const float4*)&bias[lane * 4];
            float4 w4 = *(const float4*)&fcW[lane * 4];
            p  = fmaxf(o4.x + b4.x, 0.f) * w4.x;
            p += fmaxf(o4.y + b4.y, 0.f) * w4.y;
            p += fmaxf(o4.z + b4.z, 0.f) * w4.z;
            p += fmaxf(o4.w + b4.w, 0.f) * w4.w;
        }
#pragma unroll
        for (int o = 8; o > 0; o >>= 1) p += __shfl_xor_sync(~0u, p, o);
        if (lane == 0) out[warp] = p + fcb[0];
    }
}

// =================== host orchestration ===================
extern "C" void kernel_launch(void* const* d_in, const int* in_sizes, int n_in,
                              void* d_out, int out_size) {
    const float* x        = (const float*)d_in[0];
    const int*   ei       = (const int*)  d_in[1];
    const float* W1       = (const float*)d_in[2];
    const float* att_src1 = (const float*)d_in[3];
    const float* att_dst1 = (const float*)d_in[4];
    const float* b1       = (const float*)d_in[5];
    const float* W2       = (const float*)d_in[6];
    const float* att_src2 = (const float*)d_in[7];
    const float* att_dst2 = (const float*)d_in[8];
    const float* b2       = (const float*)d_in[9];
    const float* fc_W     = (const float*)d_in[10];
    const float* fc_b     = (const float*)d_in[11];
    float* out = (float*)d_out;

    uint* x2p = nullptr;
    cudaGetSymbolAddress((void**)&x2p, g_x2h);

    // CSR build
    zero_kernel<<<NB, 256>>>();
    hist_kernel<<<(ET + 255) / 256, 256>>>(ei);
    scan1_kernel<<<NB, 256>>>();
    scan2_kernel<<<NB, 256>>>();
    fill_kernel<<<(ET + 255) / 256, 256>>>(ei);

    // layer 1
    bprep_kernel<128><<<(8 * 512 + 255) / 256, 256>>>(W1);
    gemm_att_kernel<128, false><<<(Nn + 63) / 64, 128>>>(x, att_src1, att_dst1);
    aggregate_kernel<false><<<(Nn * 32 + 255) / 256, 256>>>(b1, nullptr, nullptr, (float*)x2p);

    // layer 2 (+ fused FC head)
    bprep_kernel<64><<<(4 * 512 + 255) / 256, 256>>>(W2);
    gemm_att_kernel<64, true><<<(Nn + 63) / 64, 128>>>(x2p, att_src2, att_dst2);
    aggregate_kernel<true><<<(Nn * 32 + 255) / 256, 256>>>(b2, fc_W, fc_b, out);
}

// round 7
// speedup vs baseline: 5.2969x; 1.0674x over previous
#include <cuda_runtime.h>
#include <cuda_fp16.h>

#define Nn 50000
#define Ee 800000
#define ET (Ee + Nn)
#define NEG_SLOPE 0.2f
#define NB 196              // scan blocks: 196*256 >= 50000

typedef unsigned int uint;

// ---------------- scratch ----------------
__device__ uint   g_hh[Nn * 64];     // h as half2 units: 128 halves per node
__device__ uint   g_x2h[Nn * 32];    // layer-1 output as half2 units
__device__ float  g_asrc[Nn * 2];
__device__ float  g_adst[Nn * 2];
__device__ float2 g_e[ET];
__device__ int    g_deg[Nn];
__device__ int    g_part[NB];
__device__ int    g_rowptr[Nn + 1];
__device__ int    g_srcA[ET];
__device__ uint2  g_Bp[8 * 16 * 32];

// ---------------- helpers ----------------
__device__ __forceinline__ uint packh2(float a, float b) {
    __half2 h = __floats2half2_rn(a, b);
    return *(uint*)&h;
}
__device__ __forceinline__ void mma16(float* c, const uint* a, uint b0, uint b1) {
    asm volatile(
        "mma.sync.aligned.m16n8k16.row.col.f32.f16.f16.f32 "
        "{%0,%1,%2,%3},{%4,%5,%6,%7},{%8,%9},{%0,%1,%2,%3};"
        : "+f"(c[0]), "+f"(c[1]), "+f"(c[2]), "+f"(c[3])
        : "r"(a[0]), "r"(a[1]), "r"(a[2]), "r"(a[3]), "r"(b0), "r"(b1));
}

// =================== CSR build ===================
__global__ void zero_kernel() {       // deg = 1 accounts for the self-loop
    int i = blockIdx.x * blockDim.x + threadIdx.x;
    if (i < Nn) g_deg[i] = 1;
}
__global__ void hist_kernel(const int* __restrict__ ei) {
    int i = blockIdx.x * blockDim.x + threadIdx.x;
    if (i >= Ee / 4) return;
    int4 d = ((const int4*)(ei + Ee))[i];
    atomicAdd(&g_deg[d.x], 1);
    atomicAdd(&g_deg[d.y], 1);
    atomicAdd(&g_deg[d.z], 1);
    atomicAdd(&g_deg[d.w], 1);
}
__global__ void scan1_kernel() {
    __shared__ int sm[256];
    int t = threadIdx.x;
    int i = blockIdx.x * 256 + t;
    sm[t] = (i < Nn) ? g_deg[i] : 0;
    __syncthreads();
    for (int o = 128; o > 0; o >>= 1) {
        if (t < o) sm[t] += sm[t + o];
        __syncthreads();
    }
    if (t == 0) g_part[blockIdx.x] = sm[0];
}
__global__ void scan2_kernel() {
    __shared__ int sp[256];
    __shared__ int sd[256];
    int b = blockIdx.x, t = threadIdx.x;
    sp[t] = (t < NB && t < b) ? g_part[t] : 0;
    __syncthreads();
    for (int o = 128; o > 0; o >>= 1) {
        if (t < o) sp[t] += sp[t + o];
        __syncthreads();
    }
    int base = sp[0];
    int i = b * 256 + t;
    int v = (i < Nn) ? g_deg[i] : 0;
    sd[t] = v;
    __syncthreads();
    for (int o = 1; o < 256; o <<= 1) {
        int y = (t >= o) ? sd[t - o] : 0;
        __syncthreads();
        sd[t] += y;
        __syncthreads();
    }
    if (i < Nn) g_rowptr[i] = base + sd[t] - v;
    if (b == NB - 1 && t == 255) g_rowptr[Nn] = base + sd[255];
}
__global__ void fill_kernel(const int* __restrict__ ei) {
    int i = blockIdx.x * blockDim.x + threadIdx.x;
    if (i < Ee / 2) {
        int2 s = ((const int2*)ei)[i];
        int2 d = ((const int2*)(ei + Ee))[i];
        int o1 = atomicSub(&g_deg[d.x], 1);
        g_srcA[g_rowptr[d.x] + o1 - 1] = s.x;
        int o2 = atomicSub(&g_deg[d.y], 1);
        g_srcA[g_rowptr[d.y] + o2 - 1] = s.y;
    } else {
        int n = i - Ee / 2;
        if (n < Nn) {
            int o = atomicSub(&g_deg[n], 1);
            g_srcA[g_rowptr[n] + o - 1] = n;
        }
    }
}

// =================== B fragment prep ===================
template <int K>
__global__ void bprep_kernel(const float* __restrict__ W) {
    int e = blockIdx.x * blockDim.x + threadIdx.x;
    if (e >= (K / 16) * 512) return;
    int ks   = e >> 9;
    int rem  = e & 511;
    int tp   = rem >> 5;
    int lane = rem & 31;
    int g = lane >> 2, t = lane & 3;
    int k0 = ks * 16 + 2 * t;
    int n  = tp * 8 + g;
    uint2 p;
    p.x = packh2(W[k0 * 128 + n],       W[(k0 + 1) * 128 + n]);
    p.y = packh2(W[(k0 + 8) * 128 + n], W[(k0 + 9) * 128 + n]);
    g_Bp[e] = p;
}

// =================== GEMM (fp16 HMMA, fp32 acc) + fused attention dots ===================
template <int K, bool HALF_IN>
__global__ void __launch_bounds__(128) gemm_att_kernel(const void* __restrict__ Xv,
                                                       const float* __restrict__ asv,
                                                       const float* __restrict__ adv) {
    int w = threadIdx.x >> 5, lane = threadIdx.x & 31;
    int g = lane >> 2, t = lane & 3;
    int rowb = blockIdx.x * 64 + w * 16;
    int r0 = rowb + g, r1 = r0 + 8;
    bool p0 = r0 < Nn, p1 = r1 < Nn;
    const float* Xf = (const float*)Xv;
    const uint*  Xh = (const uint*)Xv;

    float acc[16][4] = {};
#pragma unroll
    for (int ks = 0; ks < K / 16; ks++) {
        int kA = ks * 16 + 2 * t;
        uint a[4];
        if (HALF_IN) {
            a[0] = p0 ? Xh[(r0 * K + kA) >> 1]     : 0u;
            a[1] = p1 ? Xh[(r1 * K + kA) >> 1]     : 0u;
            a[2] = p0 ? Xh[(r0 * K + kA + 8) >> 1] : 0u;
            a[3] = p1 ? Xh[(r1 * K + kA + 8) >> 1] : 0u;
        } else {
            float2 f0 = p0 ? *(const float2*)&Xf[r0 * K + kA]     : make_float2(0.f, 0.f);
            float2 f1 = p1 ? *(const float2*)&Xf[r1 * K + kA]     : make_float2(0.f, 0.f);
            float2 f2 = p0 ? *(const float2*)&Xf[r0 * K + kA + 8] : make_float2(0.f, 0.f);
            float2 f3 = p1 ? *(const float2*)&Xf[r1 * K + kA + 8] : make_float2(0.f, 0.f);
            a[0] = packh2(f0.x, f0.y);
            a[1] = packh2(f1.x, f1.y);
            a[2] = packh2(f2.x, f2.y);
            a[3] = packh2(f3.x, f3.y);
        }
        const uint2* bp = g_Bp + ks * 512 + lane;
#pragma unroll
        for (int tp = 0; tp < 16; tp++) {
            uint2 b = bp[tp * 32];
            mma16(acc[tp], a, b.x, b.y);
        }
    }

#pragma unroll
    for (int n = 0; n < 16; n++) {
        int c = n * 8 + 2 * t;
        if (p0) g_hh[(r0 * 128 + c) >> 1] = packh2(acc[n][0], acc[n][1]);
        if (p1) g_hh[(r1 * 128 + c) >> 1] = packh2(acc[n][2], acc[n][3]);
    }

    float sa[2][2] = {};
    float sd_[2][2] = {};
#pragma unroll
    for (int n = 0; n < 16; n++) {
        int c = n * 8 + 2 * t;
        float v0 = asv[c], v1 = asv[c + 1];
        float u0 = adv[c], u1 = adv[c + 1];
        int hh = n >> 3;
        sa[0][hh] += acc[n][0] * v0 + acc[n][1] * v1;
        sa[1][hh] += acc[n][2] * v0 + acc[n][3] * v1;
        sd_[0][hh] += acc[n][0] * u0 + acc[n][1] * u1;
        sd_[1][hh] += acc[n][2] * u0 + acc[n][3] * u1;
    }
#pragma unroll
    for (int rh = 0; rh < 2; rh++)
#pragma unroll
        for (int hh = 0; hh < 2; hh++) {
            sa[rh][hh] += __shfl_xor_sync(~0u, sa[rh][hh], 1);
            sa[rh][hh] += __shfl_xor_sync(~0u, sa[rh][hh], 2);
            sd_[rh][hh] += __shfl_xor_sync(~0u, sd_[rh][hh], 1);
            sd_[rh][hh] += __shfl_xor_sync(~0u, sd_[rh][hh], 2);
        }
    if (t == 0) {
        if (p0) {
            g_asrc[r0 * 2] = sa[0][0]; g_asrc[r0 * 2 + 1] = sa[0][1];
            g_adst[r0 * 2] = sd_[0][0]; g_adst[r0 * 2 + 1] = sd_[0][1];
        }
        if (p1) {
            g_asrc[r1 * 2] = sa[1][0]; g_asrc[r1 * 2 + 1] = sa[1][1];
            g_adst[r1 * 2] = sd_[1][0]; g_adst[r1 * 2 + 1] = sd_[1][1];
        }
    }
}

// =================== aggregate ===================
template <bool FC>
__global__ void aggregate_kernel(const float* __restrict__ bias,
                                 const float* __restrict__ fcW,
                                 const float* __restrict__ fcb,
                                 float* __restrict__ out) {
    int warp = (blockIdx.x * blockDim.x + threadIdx.x) >> 5;
    int lane = threadIdx.x & 31;
    if (warp >= Nn) return;
    int start = g_rowptr[warp], end = g_rowptr[warp + 1];
    float2 ad = *(const float2*)&g_adst[warp * 2];

    // pass 1: logits + exp + sum; first chunk in registers
    float s0 = 0.f, s1 = 0.f;
    int   fsrc = 0;
    float fp0 = 0.f, fp1 = 0.f;
    int i0 = start + lane;
    if (i0 < end) {
        int s = g_srcA[i0];
        float2 as = *(const float2*)&g_asrc[s * 2];
        float e0 = as.x + ad.x; e0 = e0 > 0.f ? e0 : NEG_SLOPE * e0;
        float e1 = as.y + ad.y; e1 = e1 > 0.f ? e1 : NEG_SLOPE * e1;
        fp0 = __expf(fminf(e0, 60.f));
        fp1 = __expf(fminf(e1, 60.f));
        fsrc = s;
        s0 += fp0; s1 += fp1;
        for (int i = i0 + 32; i < end; i += 32) {
            int s2 = g_srcA[i];
            float2 a2 = *(const float2*)&g_asrc[s2 * 2];
            float q0 = a2.x + ad.x; q0 = q0 > 0.f ? q0 : NEG_SLOPE * q0;
            float q1 = a2.y + ad.y; q1 = q1 > 0.f ? q1 : NEG_SLOPE * q1;
            q0 = __expf(fminf(q0, 60.f));
            q1 = __expf(fminf(q1, 60.f));
            g_e[i] = make_float2(q0, q1);
            s0 += q0; s1 += q1;
        }
    }
#pragma unroll
    for (int o = 16; o > 0; o >>= 1) {
        s0 += __shfl_xor_sync(~0u, s0, o);
        s1 += __shfl_xor_sync(~0u, s1, o);
    }
    float inv = (lane < 16) ? 1.f / (s0 + 1e-16f) : 1.f / (s1 + 1e-16f);
    bool lo = (lane < 16);

    // pass 2: weighted fp16 gather, 4x unrolled for MLP.
    // NOTE: all __shfl_sync are executed unconditionally (convergent); the
    // lane-dependent head select happens AFTER on register values.
    float4 acc = make_float4(0.f, 0.f, 0.f, 0.f);
    int cn = min(32, end - start);
    int jmax = cn & ~3;
    for (int j = 0; j < jmax; j += 4) {
        int sA = __shfl_sync(~0u, fsrc, j);
        int sB = __shfl_sync(~0u, fsrc, j + 1);
        int sC = __shfl_sync(~0u, fsrc, j + 2);
        int sD = __shfl_sync(~0u, fsrc, j + 3);
        float p0A = __shfl_sync(~0u, fp0, j),     p1A = __shfl_sync(~0u, fp1, j);
        float p0B = __shfl_sync(~0u, fp0, j + 1), p1B = __shfl_sync(~0u, fp1, j + 1);
        float p0C = __shfl_sync(~0u, fp0, j + 2), p1C = __shfl_sync(~0u, fp1, j + 2);
        float p0D = __shfl_sync(~0u, fp0, j + 3), p1D = __shfl_sync(~0u, fp1, j + 3);
        float aA = (lo ? p0A : p1A) * inv;
        float aB = (lo ? p0B : p1B) * inv;
        float aC = (lo ? p0C : p1C) * inv;
        float aD = (lo ? p0D : p1D) * inv;
        uint2 hA = *(const uint2*)&g_hh[sA * 64 + lane * 2];
        uint2 hB = *(const uint2*)&g_hh[sB * 64 + lane * 2];
        uint2 hC = *(const uint2*)&g_hh[sC * 64 + lane * 2];
        uint2 hD = *(const uint2*)&g_hh[sD * 64 + lane * 2];
        float2 f;
        f = __half22float2(*(__half2*)&hA.x); acc.x += aA * f.x; acc.y += aA * f.y;
        f = __half22float2(*(__half2*)&hA.y); acc.z += aA * f.x; acc.w += aA * f.y;
        f = __half22float2(*(__half2*)&hB.x); acc.x += aB * f.x; acc.y += aB * f.y;
        f = __half22float2(*(__half2*)&hB.y); acc.z += aB * f.x; acc.w += aB * f.y;
        f = __half22float2(*(__half2*)&hC.x); acc.x += aC * f.x; acc.y += aC * f.y;
        f = __half22float2(*(__half2*)&hC.y); acc.z += aC * f.x; acc.w += aC * f.y;
        f = __half22float2(*(__half2*)&hD.x); acc.x += aD * f.x; acc.y += aD * f.y;
        f = __half22float2(*(__half2*)&hD.y); acc.z += aD * f.x; acc.w += aD * f.y;
    }
    for (int j = jmax; j < cn; j++) {
        int   s  = __shfl_sync(~0u, fsrc, j);
        float q0 = __shfl_sync(~0u, fp0, j);
        float q1 = __shfl_sync(~0u, fp1, j);
        float a = (lo ? q0 : q1) * inv;
        uint2 hu = *(const uint2*)&g_hh[s * 64 + lane * 2];
        float2 f0 = __half22float2(*(__half2*)&hu.x);
        float2 f1 = __half22float2(*(__half2*)&hu.y);
        acc.x += a * f0.x; acc.y += a * f0.y; acc.z += a * f1.x; acc.w += a * f1.y;
    }
    // cold path: nodes with degree > 32
    for (int base = start + 32; base < end; base += 32) {
        int idx = base + lane;
        int   ls = (idx < end) ? g_srcA[idx] : 0;
        float lp0 = 0.f, lp1 = 0.f;
        if (idx < end) { float2 ev = g_e[idx]; lp0 = ev.x; lp1 = ev.y; }
        int n = min(32, end - base);
        for (int j = 0; j < n; j++) {
            int   s  = __shfl_sync(~0u, ls, j);
            float q0 = __shfl_sync(~0u, lp0, j);
            float q1 = __shfl_sync(~0u, lp1, j);
            float a = (lo ? q0 : q1) * inv;
            uint2 hu = *(const uint2*)&g_hh[s * 64 + lane * 2];
            float2 f0 = __half22float2(*(__half2*)&hu.x);
            float2 f1 = __half22float2(*(__half2*)&hu.y);
            acc.x += a * f0.x; acc.y += a * f0.y; acc.z += a * f1.x; acc.w += a * f1.y;
        }
    }

    float4 o4;
    o4.x = (acc.x + __shfl_xor_sync(~0u, acc.x, 16)) * 0.5f;
    o4.y = (acc.y + __shfl_xor_sync(~0u, acc.y, 16)) * 0.5f;
    o4.z = (acc.z + __shfl_xor_sync(~0u, acc.z, 16)) * 0.5f;
    o4.w = (acc.w + __shfl_xor_sync(~0u, acc.w, 16)) * 0.5f;

    if (!FC) {
        if (lane < 16) {
            float4 b4 = *(const float4*)&bias[lane * 4];
            o4.x = fmaxf(o4.x + b4.x, 0.f);
            o4.y = fmaxf(o4.y + b4.y, 0.f);
            o4.z = fmaxf(o4.z + b4.z, 0.f);
            o4.w = fmaxf(o4.w + b4.w, 0.f);
            uint2 p;
            p.x = packh2(o4.x, o4.y);
            p.y = packh2(o4.z, o4.w);
            *(uint2*)&((uint*)out)[warp * 32 + lane * 2] = p;
        }
    } else {
        float p = 0.f;
        if (lane < 16) {
            float4 b4 = *(const float4*)&bias[lane * 4];
            float4 w4 = *(const float4*)&fcW[lane * 4];
            p  = fmaxf(o4.x + b4.x, 0.f) * w4.x;
            p += fmaxf(o4.y + b4.y, 0.f) * w4.y;
            p += fmaxf(o4.z + b4.z, 0.f) * w4.z;
            p += fmaxf(o4.w + b4.w, 0.f) * w4.w;
        }
#pragma unroll
        for (int o = 8; o > 0; o >>= 1) p += __shfl_xor_sync(~0u, p, o);
        if (lane == 0) out[warp] = p + fcb[0];
    }
}

// =================== host orchestration ===================
extern "C" void kernel_launch(void* const* d_in, const int* in_sizes, int n_in,
                              void* d_out, int out_size) {
    const float* x        = (const float*)d_in[0];
    const int*   ei       = (const int*)  d_in[1];
    const float* W1       = (const float*)d_in[2];
    const float* att_src1 = (const float*)d_in[3];
    const float* att_dst1 = (const float*)d_in[4];
    const float* b1       = (const float*)d_in[5];
    const float* W2       = (const float*)d_in[6];
    const float* att_src2 = (const float*)d_in[7];
    const float* att_dst2 = (const float*)d_in[8];
    const float* b2       = (const float*)d_in[9];
    const float* fc_W     = (const float*)d_in[10];
    const float* fc_b     = (const float*)d_in[11];
    float* out = (float*)d_out;

    uint* x2p = nullptr;
    cudaGetSymbolAddress((void**)&x2p, g_x2h);

    static cudaStream_t s2 = nullptr;
    static cudaEvent_t evFork = nullptr, evJoin = nullptr;
    if (s2 == nullptr) {
        cudaStreamCreateWithFlags(&s2, cudaStreamNonBlocking);
        cudaEventCreateWithFlags(&evFork, cudaEventDisableTiming);
        cudaEventCreateWithFlags(&evJoin, cudaEventDisableTiming);
    }

    // fork: CSR build on s2, GEMM prep on main stream
    cudaEventRecord(evFork, 0);
    cudaStreamWaitEvent(s2, evFork, 0);

    zero_kernel<<<NB, 256, 0, s2>>>();
    hist_kernel<<<(Ee / 4 + 255) / 256, 256, 0, s2>>>(ei);
    scan1_kernel<<<NB, 256, 0, s2>>>();
    scan2_kernel<<<NB, 256, 0, s2>>>();
    fill_kernel<<<(Ee / 2 + Nn + 255) / 256, 256, 0, s2>>>(ei);
    cudaEventRecord(evJoin, s2);

    bprep_kernel<128><<<(8 * 512 + 255) / 256, 256>>>(W1);
    gemm_att_kernel<128, false><<<(Nn + 63) / 64, 128>>>(x, att_src1, att_dst1);

    // join: aggregate needs CSR + gemm1
    cudaStreamWaitEvent(0, evJoin, 0);
    aggregate_kernel<false><<<(Nn * 32 + 255) / 256, 256>>>(b1, nullptr, nullptr, (float*)x2p);

    bprep_kernel<64><<<(4 * 512 + 255) / 256, 256>>>(W2);
    gemm_att_kernel<64, true><<<(Nn + 63) / 64, 128>>>(x2p, att_src2, att_dst2);
    aggregate_kernel<true><<<(Nn * 32 + 255) / 256, 256>>>(b2, fc_W, fc_b, out);
}

// round 8
// speedup vs baseline: 5.4838x; 1.0353x over previous
#include <cuda_runtime.h>
#include <cuda_fp16.h>

#define Nn 50000
#define Ee 800000
#define ET (Ee + Nn)
#define NEG_SLOPE 0.2f
#define NB 196              // scan blocks: 196*256 >= 50000

typedef unsigned int uint;

// ---------------- scratch ----------------
__device__ uint   g_hh[Nn * 64];     // h as half2 units
__device__ uint   g_x2h[Nn * 32];    // layer-1 output as half2 units
__device__ float  g_asrc[Nn * 2];
__device__ float  g_adst[Nn * 2];
__device__ float2 g_e[ET];
__device__ int    g_deg[Nn];         // INVARIANT: all zeros outside hist->fill window
__device__ int    g_part[NB];
__device__ int    g_rowptr[Nn + 1];
__device__ int    g_srcA[ET];
__device__ uint2  g_Bp1[8 * 512];    // layer-1 W fragments (K=128)
__device__ uint2  g_Bp2[4 * 512];    // layer-2 W fragments (K=64)

// ---------------- helpers ----------------
__device__ __forceinline__ uint packh2(float a, float b) {
    __half2 h = __floats2half2_rn(a, b);
    return *(uint*)&h;
}
__device__ __forceinline__ void mma16(float* c, const uint* a, uint b0, uint b1) {
    asm volatile(
        "mma.sync.aligned.m16n8k16.row.col.f32.f16.f16.f32 "
        "{%0,%1,%2,%3},{%4,%5,%6,%7},{%8,%9},{%0,%1,%2,%3};"
        : "+f"(c[0]), "+f"(c[1]), "+f"(c[2]), "+f"(c[3])
        : "r"(a[0]), "r"(a[1]), "r"(a[2]), "r"(a[3]), "r"(b0), "r"(b1));
}

// =================== CSR build ===================
__global__ void hist_kernel(const int* __restrict__ ei) {
    int i = blockIdx.x * blockDim.x + threadIdx.x;
    if (i >= Ee / 4) return;
    int4 d = ((const int4*)(ei + Ee))[i];
    atomicAdd(&g_deg[d.x], 1);
    atomicAdd(&g_deg[d.y], 1);
    atomicAdd(&g_deg[d.z], 1);
    atomicAdd(&g_deg[d.w], 1);
}

__global__ void scan1_kernel() {     // per-block sum of deg
    __shared__ int ws[8];
    int t = threadIdx.x, lane = t & 31, wid = t >> 5;
    int i = blockIdx.x * 256 + t;
    int v = (i < Nn) ? g_deg[i] : 0;
#pragma unroll
    for (int o = 16; o > 0; o >>= 1) v += __shfl_xor_sync(~0u, v, o);
    if (lane == 0) ws[wid] = v;
    __syncthreads();
    if (t == 0) {
        int s = 0;
#pragma unroll
        for (int k = 0; k < 8; k++) s += ws[k];
        g_part[blockIdx.x] = s;
    }
}

__global__ void scan2_kernel() {     // rowptr[i] = exclscan(deg)[i] + i  (self-loop slots)
    __shared__ int wsA[8];
    __shared__ int wsB[8];
    __shared__ int base_sh;
    int b = blockIdx.x, t = threadIdx.x, lane = t & 31, wid = t >> 5;
    // base = sum of partials of blocks before b
    int p = (t < b) ? g_part[t] : 0;       // NB <= 256
#pragma unroll
    for (int o = 16; o > 0; o >>= 1) p += __shfl_xor_sync(~0u, p, o);
    if (lane == 0) wsA[wid] = p;
    __syncthreads();
    if (t == 0) {
        int s = 0;
#pragma unroll
        for (int k = 0; k < 8; k++) s += wsA[k];
        base_sh = s;
    }
    // block-local inclusive scan of deg
    int i = b * 256 + t;
    int v = (i < Nn) ? g_deg[i] : 0;
    int s = v;
#pragma unroll
    for (int o = 1; o < 32; o <<= 1) {
        int y = __shfl_up_sync(~0u, s, o);
        if (lane >= o) s += y;
    }
    if (lane == 31) wsB[wid] = s;
    __syncthreads();
    int add = 0;
    for (int k = 0; k < wid; k++) add += wsB[k];
    int excl = base_sh + add + (s - v);
    if (i < Nn) g_rowptr[i] = excl + i;
    if (b == NB - 1 && t == 255) g_rowptr[Nn] = base_sh + add + s + Nn;
}

__global__ void fill_kernel(const int* __restrict__ ei) {
    int i = blockIdx.x * blockDim.x + threadIdx.x;
    if (i < Ee / 2) {
        int2 s = ((const int2*)ei)[i];
        int2 d = ((const int2*)(ei + Ee))[i];
        int o1 = atomicSub(&g_deg[d.x], 1);       // o1 in [1..deg] -> slots rowptr+1..rowptr+deg
        g_srcA[g_rowptr[d.x] + o1] = s.x;
        int o2 = atomicSub(&g_deg[d.y], 1);
        g_srcA[g_rowptr[d.y] + o2] = s.y;
    } else {
        int n = i - Ee / 2;
        if (n < Nn) g_srcA[g_rowptr[n]] = n;      // self-loop slot, no atomic
    }
    // after this kernel g_deg[] == 0 everywhere (invariant restored)
}

// =================== B fragment prep ===================
template <int K>
__global__ void bprep_kernel(const float* __restrict__ W, uint2* __restrict__ Bp) {
    int e = blockIdx.x * blockDim.x + threadIdx.x;
    if (e >= (K / 16) * 512) return;
    int ks   = e >> 9;
    int rem  = e & 511;
    int tp   = rem >> 5;
    int lane = rem & 31;
    int g = lane >> 2, t = lane & 3;
    int k0 = ks * 16 + 2 * t;
    int n  = tp * 8 + g;
    uint2 p;
    p.x = packh2(W[k0 * 128 + n],       W[(k0 + 1) * 128 + n]);
    p.y = packh2(W[(k0 + 8) * 128 + n], W[(k0 + 9) * 128 + n]);
    Bp[e] = p;
}

// =================== GEMM (fp16 HMMA, fp32 acc) + fused attention dots ===================
template <int K, bool HALF_IN>
__global__ void __launch_bounds__(128) gemm_att_kernel(const void* __restrict__ Xv,
                                                       const uint2* __restrict__ Bp,
                                                       const float* __restrict__ asv,
                                                       const float* __restrict__ adv) {
    int w = threadIdx.x >> 5, lane = threadIdx.x & 31;
    int g = lane >> 2, t = lane & 3;
    int rowb = blockIdx.x * 64 + w * 16;
    int r0 = rowb + g, r1 = r0 + 8;
    bool p0 = r0 < Nn, p1 = r1 < Nn;
    const float* Xf = (const float*)Xv;
    const uint*  Xh = (const uint*)Xv;

    float acc[16][4] = {};
#pragma unroll
    for (int ks = 0; ks < K / 16; ks++) {
        int kA = ks * 16 + 2 * t;
        uint a[4];
        if (HALF_IN) {
            a[0] = p0 ? Xh[(r0 * K + kA) >> 1]     : 0u;
            a[1] = p1 ? Xh[(r1 * K + kA) >> 1]     : 0u;
            a[2] = p0 ? Xh[(r0 * K + kA + 8) >> 1] : 0u;
            a[3] = p1 ? Xh[(r1 * K + kA + 8) >> 1] : 0u;
        } else {
            float2 f0 = p0 ? *(const float2*)&Xf[r0 * K + kA]     : make_float2(0.f, 0.f);
            float2 f1 = p1 ? *(const float2*)&Xf[r1 * K + kA]     : make_float2(0.f, 0.f);
            float2 f2 = p0 ? *(const float2*)&Xf[r0 * K + kA + 8] : make_float2(0.f, 0.f);
            float2 f3 = p1 ? *(const float2*)&Xf[r1 * K + kA + 8] : make_float2(0.f, 0.f);
            a[0] = packh2(f0.x, f0.y);
            a[1] = packh2(f1.x, f1.y);
            a[2] = packh2(f2.x, f2.y);
            a[3] = packh2(f3.x, f3.y);
        }
        const uint2* bp = Bp + ks * 512 + lane;
#pragma unroll
        for (int tp = 0; tp < 16; tp++) {
            uint2 b = bp[tp * 32];
            mma16(acc[tp], a, b.x, b.y);
        }
    }

#pragma unroll
    for (int n = 0; n < 16; n++) {
        int c = n * 8 + 2 * t;
        if (p0) g_hh[(r0 * 128 + c) >> 1] = packh2(acc[n][0], acc[n][1]);
        if (p1) g_hh[(r1 * 128 + c) >> 1] = packh2(acc[n][2], acc[n][3]);
    }

    float sa[2][2] = {};
    float sd_[2][2] = {};
#pragma unroll
    for (int n = 0; n < 16; n++) {
        int c = n * 8 + 2 * t;
        float v0 = asv[c], v1 = asv[c + 1];
        float u0 = adv[c], u1 = adv[c + 1];
        int hh = n >> 3;
        sa[0][hh] += acc[n][0] * v0 + acc[n][1] * v1;
        sa[1][hh] += acc[n][2] * v0 + acc[n][3] * v1;
        sd_[0][hh] += acc[n][0] * u0 + acc[n][1] * u1;
        sd_[1][hh] += acc[n][2] * u0 + acc[n][3] * u1;
    }
#pragma unroll
    for (int rh = 0; rh < 2; rh++)
#pragma unroll
        for (int hh = 0; hh < 2; hh++) {
            sa[rh][hh] += __shfl_xor_sync(~0u, sa[rh][hh], 1);
            sa[rh][hh] += __shfl_xor_sync(~0u, sa[rh][hh], 2);
            sd_[rh][hh] += __shfl_xor_sync(~0u, sd_[rh][hh], 1);
            sd_[rh][hh] += __shfl_xor_sync(~0u, sd_[rh][hh], 2);
        }
    if (t == 0) {
        if (p0) {
            g_asrc[r0 * 2] = sa[0][0]; g_asrc[r0 * 2 + 1] = sa[0][1];
            g_adst[r0 * 2] = sd_[0][0]; g_adst[r0 * 2 + 1] = sd_[0][1];
        }
        if (p1) {
            g_asrc[r1 * 2] = sa[1][0]; g_asrc[r1 * 2 + 1] = sa[1][1];
            g_adst[r1 * 2] = sd_[1][0]; g_adst[r1 * 2 + 1] = sd_[1][1];
        }
    }
}

// =================== aggregate ===================
template <bool FC>
__global__ void aggregate_kernel(const float* __restrict__ bias,
                                 const float* __restrict__ fcW,
                                 const float* __restrict__ fcb,
                                 float* __restrict__ out) {
    int warp = (blockIdx.x * blockDim.x + threadIdx.x) >> 5;
    int lane = threadIdx.x & 31;
    if (warp >= Nn) return;
    int start = g_rowptr[warp], end = g_rowptr[warp + 1];
    float2 ad = *(const float2*)&g_adst[warp * 2];

    // pass 1: logits + exp + sum; first chunk in registers
    float s0 = 0.f, s1 = 0.f;
    int   fsrc = 0;
    float fp0 = 0.f, fp1 = 0.f;
    int i0 = start + lane;
    if (i0 < end) {
        int s = g_srcA[i0];
        float2 as = *(const float2*)&g_asrc[s * 2];
        float e0 = as.x + ad.x; e0 = e0 > 0.f ? e0 : NEG_SLOPE * e0;
        float e1 = as.y + ad.y; e1 = e1 > 0.f ? e1 : NEG_SLOPE * e1;
        fp0 = __expf(fminf(e0, 60.f));
        fp1 = __expf(fminf(e1, 60.f));
        fsrc = s;
        s0 += fp0; s1 += fp1;
        for (int i = i0 + 32; i < end; i += 32) {
            int s2 = g_srcA[i];
            float2 a2 = *(const float2*)&g_asrc[s2 * 2];
            float q0 = a2.x + ad.x; q0 = q0 > 0.f ? q0 : NEG_SLOPE * q0;
            float q1 = a2.y + ad.y; q1 = q1 > 0.f ? q1 : NEG_SLOPE * q1;
            q0 = __expf(fminf(q0, 60.f));
            q1 = __expf(fminf(q1, 60.f));
            g_e[i] = make_float2(q0, q1);
            s0 += q0; s1 += q1;
        }
    }
#pragma unroll
    for (int o = 16; o > 0; o >>= 1) {
        s0 += __shfl_xor_sync(~0u, s0, o);
        s1 += __shfl_xor_sync(~0u, s1, o);
    }
    float inv = (lane < 16) ? 1.f / (s0 + 1e-16f) : 1.f / (s1 + 1e-16f);
    bool lo = (lane < 16);

    // pass 2: weighted fp16 gather, 4x unrolled; shuffles convergent
    float4 acc = make_float4(0.f, 0.f, 0.f, 0.f);
    int cn = min(32, end - start);
    int jmax = cn & ~3;
    for (int j = 0; j < jmax; j += 4) {
        int sA = __shfl_sync(~0u, fsrc, j);
        int sB = __shfl_sync(~0u, fsrc, j + 1);
        int sC = __shfl_sync(~0u, fsrc, j + 2);
        int sD = __shfl_sync(~0u, fsrc, j + 3);
        float p0A = __shfl_sync(~0u, fp0, j),     p1A = __shfl_sync(~0u, fp1, j);
        float p0B = __shfl_sync(~0u, fp0, j + 1), p1B = __shfl_sync(~0u, fp1, j + 1);
        float p0C = __shfl_sync(~0u, fp0, j + 2), p1C = __shfl_sync(~0u, fp1, j + 2);
        float p0D = __shfl_sync(~0u, fp0, j + 3), p1D = __shfl_sync(~0u, fp1, j + 3);
        float aA = (lo ? p0A : p1A) * inv;
        float aB = (lo ? p0B : p1B) * inv;
        float aC = (lo ? p0C : p1C) * inv;
        float aD = (lo ? p0D : p1D) * inv;
        uint2 hA = *(const uint2*)&g_hh[sA * 64 + lane * 2];
        uint2 hB = *(const uint2*)&g_hh[sB * 64 + lane * 2];
        uint2 hC = *(const uint2*)&g_hh[sC * 64 + lane * 2];
        uint2 hD = *(const uint2*)&g_hh[sD * 64 + lane * 2];
        float2 f;
        f = __half22float2(*(__half2*)&hA.x); acc.x += aA * f.x; acc.y += aA * f.y;
        f = __half22float2(*(__half2*)&hA.y); acc.z += aA * f.x; acc.w += aA * f.y;
        f = __half22float2(*(__half2*)&hB.x); acc.x += aB * f.x; acc.y += aB * f.y;
        f = __half22float2(*(__half2*)&hB.y); acc.z += aB * f.x; acc.w += aB * f.y;
        f = __half22float2(*(__half2*)&hC.x); acc.x += aC * f.x; acc.y += aC * f.y;
        f = __half22float2(*(__half2*)&hC.y); acc.z += aC * f.x; acc.w += aC * f.y;
        f = __half22float2(*(__half2*)&hD.x); acc.x += aD * f.x; acc.y += aD * f.y;
        f = __half22float2(*(__half2*)&hD.y); acc.z += aD * f.x; acc.w += aD * f.y;
    }
    for (int j = jmax; j < cn; j++) {
        int   s  = __shfl_sync(~0u, fsrc, j);
        float q0 = __shfl_sync(~0u, fp0, j);
        float q1 = __shfl_sync(~0u, fp1, j);
        float a = (lo ? q0 : q1) * inv;
        uint2 hu = *(const uint2*)&g_hh[s * 64 + lane * 2];
        float2 f0 = __half22float2(*(__half2*)&hu.x);
        float2 f1 = __half22float2(*(__half2*)&hu.y);
        acc.x += a * f0.x; acc.y += a * f0.y; acc.z += a * f1.x; acc.w += a * f1.y;
    }
    // cold path: degree > 32
    for (int base = start + 32; base < end; base += 32) {
        int idx = base + lane;
        int   ls = (idx < end) ? g_srcA[idx] : 0;
        float lp0 = 0.f, lp1 = 0.f;
        if (idx < end) { float2 ev = g_e[idx]; lp0 = ev.x; lp1 = ev.y; }
        int n = min(32, end - base);
        for (int j = 0; j < n; j++) {
            int   s  = __shfl_sync(~0u, ls, j);
            float q0 = __shfl_sync(~0u, lp0, j);
            float q1 = __shfl_sync(~0u, lp1, j);
            float a = (lo ? q0 : q1) * inv;
            uint2 hu = *(const uint2*)&g_hh[s * 64 + lane * 2];
            float2 f0 = __half22float2(*(__half2*)&hu.x);
            float2 f1 = __half22float2(*(__half2*)&hu.y);
            acc.x += a * f0.x; acc.y += a * f0.y; acc.z += a * f1.x; acc.w += a * f1.y;
        }
    }

    float4 o4;
    o4.x = (acc.x + __shfl_xor_sync(~0u, acc.x, 16)) * 0.5f;
    o4.y = (acc.y + __shfl_xor_sync(~0u, acc.y, 16)) * 0.5f;
    o4.z = (acc.z + __shfl_xor_sync(~0u, acc.z, 16)) * 0.5f;
    o4.w = (acc.w + __shfl_xor_sync(~0u, acc.w, 16)) * 0.5f;

    if (!FC) {
        if (lane < 16) {
            float4 b4 = *(const float4*)&bias[lane * 4];
            o4.x = fmaxf(o4.x + b4.x, 0.f);
            o4.y = fmaxf(o4.y + b4.y, 0.f);
            o4.z = fmaxf(o4.z + b4.z, 0.f);
            o4.w = fmaxf(o4.w + b4.w, 0.f);
            uint2 p;
            p.x = packh2(o4.x, o4.y);
            p.y = packh2(o4.z, o4.w);
            *(uint2*)&((uint*)out)[warp * 32 + lane * 2] = p;
        }
    } else {
        float p = 0.f;
        if (lane < 16) {
            float4 b4 = *(const float4*)&bias[lane * 4];
            float4 w4 = *(const float4*)&fcW[lane * 4];
            p  = fmaxf(o4.x + b4.x, 0.f) * w4.x;
            p += fmaxf(o4.y + b4.y, 0.f) * w4.y;
            p += fmaxf(o4.z + b4.z, 0.f) * w4.z;
            p += fmaxf(o4.w + b4.w, 0.f) * w4.w;
        }
#pragma unroll
        for (int o = 8; o > 0; o >>= 1) p += __shfl_xor_sync(~0u, p, o);
        if (lane == 0) out[warp] = p + fcb[0];
    }
}

// =================== host orchestration ===================
extern "C" void kernel_launch(void* const* d_in, const int* in_sizes, int n_in,
                              void* d_out, int out_size) {
    const float* x        = (const float*)d_in[0];
    const int*   ei       = (const int*)  d_in[1];
    const float* W1       = (const float*)d_in[2];
    const float* att_src1 = (const float*)d_in[3];
    const float* att_dst1 = (const float*)d_in[4];
    const float* b1       = (const float*)d_in[5];
    const float* W2       = (const float*)d_in[6];
    const float* att_src2 = (const float*)d_in[7];
    const float* att_dst2 = (const float*)d_in[8];
    const float* b2       = (const float*)d_in[9];
    const float* fc_W     = (const float*)d_in[10];
    const float* fc_b     = (const float*)d_in[11];
    float* out = (float*)d_out;

    uint*  x2p = nullptr;
    uint2* bp1 = nullptr;
    uint2* bp2 = nullptr;
    cudaGetSymbolAddress((void**)&x2p, g_x2h);
    cudaGetSymbolAddress((void**)&bp1, g_Bp1);
    cudaGetSymbolAddress((void**)&bp2, g_Bp2);

    static cudaStream_t s2 = nullptr;
    static cudaEvent_t evFork = nullptr, evG = nullptr;
    if (s2 == nullptr) {
        cudaStreamCreateWithFlags(&s2, cudaStreamNonBlocking);
        cudaEventCreateWithFlags(&evFork, cudaEventDisableTiming);
        cudaEventCreateWithFlags(&evG, cudaEventDisableTiming);
    }

    // fork: main stream runs the (longer) CSR chain; s2 runs bpreps + gemm1
    cudaEventRecord(evFork, 0);
    cudaStreamWaitEvent(s2, evFork, 0);

    // --- main: CSR (deg starts at 0 by countdown invariant) ---
    hist_kernel<<<(Ee / 4 + 255) / 256, 256>>>(ei);
    scan1_kernel<<<NB, 256>>>();
    scan2_kernel<<<NB, 256>>>();
    fill_kernel<<<(Ee / 2 + Nn + 255) / 256, 256>>>(ei);

    // --- s2: weight prep for BOTH layers + layer-1 GEMM ---
    bprep_kernel<128><<<(8 * 512 + 255) / 256, 256, 0, s2>>>(W1, bp1);
    bprep_kernel<64><<<(4 * 512 + 255) / 256, 256, 0, s2>>>(W2, bp2);
    gemm_att_kernel<128, false><<<(Nn + 63) / 64, 128, 0, s2>>>(x, bp1, att_src1, att_dst1);
    cudaEventRecord(evG, s2);

    // join on main: aggregate needs CSR (main) + gemm1 (s2)
    cudaStreamWaitEvent(0, evG, 0);
    aggregate_kernel<false><<<(Nn * 32 + 255) / 256, 256>>>(b1, nullptr, nullptr, (float*)x2p);

    gemm_att_kernel<64, true><<<(Nn + 63) / 64, 128>>>(x2p, bp2, att_src2, att_dst2);
    aggregate_kernel<true><<<(Nn * 32 + 255) / 256, 256>>>(b2, fc_W, fc_b, out);
}